// round 1
// baseline (speedup 1.0000x reference)
#include <cuda_runtime.h>
#include <math.h>

#define BB 8
#define LL 512
#define DD 128
#define UU 32
#define EPSF 1e-7f

// scratch (no allocs allowed)
__device__ float g_wtv[DD];
__device__ float g_wxv[DD];
__device__ float g_c;
__device__ float g_qs[BB*LL];
__device__ float g_ks[BB*LL];
__device__ float g_ek[BB*LL];
__device__ float g_P0[BB*(LL+1)*DD];   // prefix of x over s
__device__ float g_P1[BB*(LL+1)*DD];   // prefix of exp(ks)*x over s
__device__ float g_Pk[BB*(LL+1)];      // prefix of exp(ks)

// K0: wtv = Wt @ Wa, wxv = Wx @ Wa, c = bh . Wa + ba      (1 block, 128 thr)
__global__ void k0_fold(const float* __restrict__ Wt, const float* __restrict__ Wx,
                        const float* __restrict__ bh, const float* __restrict__ Wa,
                        const float* __restrict__ ba) {
    int d = threadIdx.x;
    float at = 0.f, ax = 0.f;
#pragma unroll
    for (int u = 0; u < UU; u++) {
        float wa = Wa[u];
        at += Wt[d*UU + u] * wa;
        ax += Wx[d*UU + u] * wa;
    }
    g_wtv[d] = at;
    g_wxv[d] = ax;
    if (d == 0) {
        float c = ba[0];
#pragma unroll
        for (int u = 0; u < UU; u++) c += bh[u] * Wa[u];
        g_c = c;
    }
}

// K1: per-token scalars qs, ks, ek=exp(ks). Warp per token. grid=1024, blk=128
__global__ void k1_scalars(const float* __restrict__ x) {
    int gwarp = (blockIdx.x * blockDim.x + threadIdx.x) >> 5;
    int lane  = threadIdx.x & 31;
    if (gwarp >= BB*LL) return;
    const float4* xr = reinterpret_cast<const float4*>(x + (size_t)gwarp * DD);
    float4 xv = xr[lane];
    float4 wt = reinterpret_cast<const float4*>(g_wtv)[lane];
    float4 wx = reinterpret_cast<const float4*>(g_wxv)[lane];
    float q = xv.x*wt.x + xv.y*wt.y + xv.z*wt.z + xv.w*wt.w;
    float k = xv.x*wx.x + xv.y*wx.y + xv.z*wx.z + xv.w*wx.w;
#pragma unroll
    for (int o = 16; o; o >>= 1) {
        q += __shfl_down_sync(0xFFFFFFFFu, q, o);
        k += __shfl_down_sync(0xFFFFFFFFu, k, o);
    }
    if (lane == 0) {
        g_qs[gwarp] = q;
        g_ks[gwarp] = k;
        g_ek[gwarp] = expf(k);
    }
}

// K2: per-batch prefix sums along s. grid=8, blk=128 (thread = d)
__global__ void k2_prefix(const float* __restrict__ x) {
    int b = blockIdx.x;
    int d = threadIdx.x;
    __shared__ float s_ek[LL];
    for (int i = d; i < LL; i += DD) s_ek[i] = g_ek[b*LL + i];
    __syncthreads();

    const float* xb = x + (size_t)b * LL * DD;
    size_t base = (size_t)b * (LL+1) * DD;
    g_P0[base + d] = 0.f;
    g_P1[base + d] = 0.f;
    if (d == 0) {
        float rk = 0.f;
        g_Pk[b*(LL+1)] = 0.f;
#pragma unroll 8
        for (int s = 0; s < LL; s++) {
            rk += s_ek[s];
            g_Pk[b*(LL+1) + s + 1] = rk;
        }
    }
    float r0 = 0.f, r1 = 0.f;
#pragma unroll 8
    for (int s = 0; s < LL; s++) {
        float xv = __ldg(xb + (size_t)s*DD + d);
        float e  = s_ek[s];
        r0 += xv;
        r1 += e * xv;
        g_P0[base + (size_t)(s+1)*DD + d] = r0;
        g_P1[base + (size_t)(s+1)*DD + d] = r1;
    }
}

// K3: output. Block per query (b,t), thread = d. grid=4096, blk=128
__global__ void k3_out(const float* __restrict__ x, float* __restrict__ out) {
    int bt = blockIdx.x;
    int b = bt / LL;
    int t = bt % LL;
    int tid = threadIdx.x;

    int lo = max(0, t - 63);
    int hi = min(LL - 1, t + 64);
    int wc = hi - lo + 1;

    // window max of ks (<=128 values, one per thread)
    float v = -INFINITY;
    if (tid < wc) v = g_ks[b*LL + lo + tid];
#pragma unroll
    for (int o = 16; o; o >>= 1) v = fmaxf(v, __shfl_down_sync(0xFFFFFFFFu, v, o));
    __shared__ float warpmax[4];
    if ((tid & 31) == 0) warpmax[tid >> 5] = v;
    __syncthreads();

    __shared__ float sA, sE, sInvZ;
    if (tid == 0) {
        float mk = fmaxf(fmaxf(warpmax[0], warpmax[1]), fmaxf(warpmax[2], warpmax[3]));
        float qc = g_qs[b*LL + t] + g_c;
        float m  = fmaxf(0.f, qc + mk);     // masked entries are 0, always present
        float A  = expf(qc - m);            // in-window common factor
        float E  = expf(-m);                // weight of each masked key
        float S1 = g_Pk[b*(LL+1) + hi + 1] - g_Pk[b*(LL+1) + lo];
        float Z  = A * S1 + E * (float)(LL - wc) + EPSF;
        sA = A; sE = E; sInvZ = 1.f / Z;
    }
    __syncthreads();

    size_t base = (size_t)b * (LL+1) * DD;
    float V1  = g_P1[base + (size_t)(hi+1)*DD + tid] - g_P1[base + (size_t)lo*DD + tid];
    float V0  = g_P0[base + (size_t)(hi+1)*DD + tid] - g_P0[base + (size_t)lo*DD + tid];
    float tot = g_P0[base + (size_t)LL*DD + tid];

    out[(size_t)bt * DD + tid] = (sA * V1 + sE * (tot - V0)) * sInvZ;
}

extern "C" void kernel_launch(void* const* d_in, const int* in_sizes, int n_in,
                              void* d_out, int out_size) {
    const float* x  = (const float*)d_in[0];   // [B,L,D]
    const float* Wt = (const float*)d_in[1];   // [D,U]
    const float* Wx = (const float*)d_in[2];   // [D,U]
    const float* bh = (const float*)d_in[3];   // [U]
    const float* Wa = (const float*)d_in[4];   // [U,1]
    const float* ba = (const float*)d_in[5];   // [1]
    float* out = (float*)d_out;                // [B,L,D]

    k0_fold<<<1, DD>>>(Wt, Wx, bh, Wa, ba);
    k1_scalars<<<(BB*LL*32)/128, 128>>>(x);
    k2_prefix<<<BB, DD>>>(x);
    k3_out<<<BB*LL, DD>>>(x, out);
}

// round 2
// speedup vs baseline: 1.0962x; 1.0962x over previous
#include <cuda_runtime.h>
#include <math.h>

#define BB 8
#define LL 512
#define DD 128
#define UU 32
#define EPSF 1e-7f
#define NCH 4           // s-chunks in P scan
#define CHS (LL/NCH)    // 128 rows per chunk

// scratch (no allocs allowed)
__device__ float g_P0[BB*(LL+1)*DD];   // prefix of x over s
__device__ float g_P1[BB*(LL+1)*DD];   // prefix of exp(ks)*x over s
__device__ float g_A[BB*LL];           // exp(qc-m)/Z per query
__device__ float g_E[BB*LL];           // exp(-m)/Z per query

// ---------------------------------------------------------------------------
// K12: one block per batch, 512 threads.
//   fold weights -> per-token scalars -> Pk scan + softmax scalars -> P0/P1
// ---------------------------------------------------------------------------
__global__ __launch_bounds__(512, 1)
void k12(const float* __restrict__ x,
         const float* __restrict__ Wt, const float* __restrict__ Wx,
         const float* __restrict__ bh, const float* __restrict__ Wa,
         const float* __restrict__ ba) {
    int b   = blockIdx.x;
    int tid = threadIdx.x;

    __shared__ __align__(16) float swt[DD], swx[DD];
    __shared__ float sqs[LL], sks[LL], sek[LL];
    __shared__ float scan[2][LL];
    __shared__ float cmax[LL/16];
    __shared__ float T0[NCH][DD], T1[NCH][DD];
    __shared__ float sc;

    // --- fold weights (redundant across 8 blocks; trivial) ---
    if (tid < DD) {
        float at = 0.f, ax = 0.f;
#pragma unroll
        for (int u = 0; u < UU; u++) {
            float wa = Wa[u];
            at += Wt[tid*UU + u] * wa;
            ax += Wx[tid*UU + u] * wa;
        }
        swt[tid] = at;
        swx[tid] = ax;
    }
    if (tid == 0) {
        float c = ba[0];
#pragma unroll
        for (int u = 0; u < UU; u++) c += bh[u] * Wa[u];
        sc = c;
    }
    __syncthreads();

    // --- per-token scalars: thread = token ---
    const float* xb = x + (size_t)b * LL * DD;
    {
        const float4* xr  = reinterpret_cast<const float4*>(xb + (size_t)tid * DD);
        const float4* wt4 = reinterpret_cast<const float4*>(swt);
        const float4* wx4 = reinterpret_cast<const float4*>(swx);
        float q = 0.f, k = 0.f;
#pragma unroll 8
        for (int i = 0; i < DD/4; i++) {
            float4 xv = xr[i];
            float4 wt = wt4[i];
            float4 wx = wx4[i];
            q += xv.x*wt.x + xv.y*wt.y + xv.z*wt.z + xv.w*wt.w;
            k += xv.x*wx.x + xv.y*wx.y + xv.z*wx.z + xv.w*wx.w;
        }
        sqs[tid] = q;
        sks[tid] = k;
        sek[tid] = expf(k);
        scan[0][tid] = sek[tid];
    }
    __syncthreads();

    // chunk maxima of ks (chunks of 16) for fast window-max
    if (tid < LL/16) {
        float m = sks[tid*16];
#pragma unroll
        for (int i = 1; i < 16; i++) m = fmaxf(m, sks[tid*16 + i]);
        cmax[tid] = m;
    }

    // --- Hillis-Steele inclusive scan of ek (9 steps) ---
    int cur = 0;
#pragma unroll
    for (int off = 1; off < LL; off <<= 1) {
        float v = scan[cur][tid];
        if (tid >= off) v += scan[cur][tid - off];
        scan[cur ^ 1][tid] = v;
        cur ^= 1;
        __syncthreads();
    }

    // --- per-query softmax scalars (thread = query t) ---
    {
        int t  = tid;
        int lo = max(0, t - 63);
        int hi = min(LL - 1, t + 64);
        int wc = hi - lo + 1;

        float wm = -INFINITY;
        int c0 = lo >> 4, c1 = hi >> 4;
        if (c0 == c1) {
            for (int s = lo; s <= hi; s++) wm = fmaxf(wm, sks[s]);
        } else {
            int e0 = (c0 + 1) << 4;
            for (int s = lo; s < e0; s++) wm = fmaxf(wm, sks[s]);
            for (int c = c0 + 1; c < c1; c++) wm = fmaxf(wm, cmax[c]);
            for (int s = c1 << 4; s <= hi; s++) wm = fmaxf(wm, sks[s]);
        }

        float qc = sqs[t] + sc;
        float m  = fmaxf(0.f, qc + wm);     // masked entries score 0, always present
        float A  = expf(qc - m);
        float E  = expf(-m);
        float S1 = scan[cur][hi] - (lo > 0 ? scan[cur][lo-1] : 0.f);
        float Z  = A * S1 + E * (float)(LL - wc) + EPSF;
        float iv = 1.f / Z;
        g_A[b*LL + t] = A * iv;
        g_E[b*LL + t] = E * iv;
    }

    // --- P0/P1 prefix over s: 4 chunks x 128 d ---
    int c = tid >> 7;        // chunk 0..3
    int d = tid & (DD-1);    // feature

    // pass 1: chunk totals
    {
        float r0 = 0.f, r1 = 0.f;
        int s0 = c * CHS;
#pragma unroll 8
        for (int s = s0; s < s0 + CHS; s++) {
            float xv = __ldg(xb + (size_t)s*DD + d);
            r0 += xv;
            r1 += sek[s] * xv;
        }
        T0[c][d] = r0;
        T1[c][d] = r1;
    }
    __syncthreads();

    // offsets for this chunk
    float o0 = 0.f, o1 = 0.f;
    for (int cc = 0; cc < c; cc++) { o0 += T0[cc][d]; o1 += T1[cc][d]; }

    // pass 2: write global-corrected prefixes (L2-hot reload of x)
    {
        size_t base = (size_t)b * (LL+1) * DD;
        if (c == 0) { g_P0[base + d] = 0.f; g_P1[base + d] = 0.f; }
        float r0 = o0, r1 = o1;
        int s0 = c * CHS;
#pragma unroll 8
        for (int s = s0; s < s0 + CHS; s++) {
            float xv = __ldg(xb + (size_t)s*DD + d);
            r0 += xv;
            r1 += sek[s] * xv;
            g_P0[base + (size_t)(s+1)*DD + d] = r0;
            g_P1[base + (size_t)(s+1)*DD + d] = r1;
        }
    }
}

// ---------------------------------------------------------------------------
// K3: pure streaming epilogue. Thread = 4 output elements (float4).
// out[bt,d] = gA[bt]*(P1[hi+1]-P1[lo]) + gE[bt]*(tot - (P0[hi+1]-P0[lo]))
// ---------------------------------------------------------------------------
__global__ __launch_bounds__(256)
void k3_out(float* __restrict__ out) {
    int idx = blockIdx.x * blockDim.x + threadIdx.x;   // 0 .. BB*LL*DD/4-1
    int bt  = idx >> 5;                                // 32 float4 per query row
    int d4  = (idx & 31);                              // float4 index within row
    int b   = bt >> 9;
    int t   = bt & (LL-1);

    int lo = max(0, t - 63);
    int hi = min(LL - 1, t + 64);

    size_t base = (size_t)b * (LL+1) * DD;
    const float4* P1 = reinterpret_cast<const float4*>(g_P1);
    const float4* P0 = reinterpret_cast<const float4*>(g_P0);

    size_t rHi = (base + (size_t)(hi+1)*DD) >> 2;
    size_t rLo = (base + (size_t)lo*DD) >> 2;
    size_t rTt = (base + (size_t)LL*DD) >> 2;

    float4 v1h = P1[rHi + d4], v1l = P1[rLo + d4];
    float4 v0h = P0[rHi + d4], v0l = P0[rLo + d4];
    float4 tot = P0[rTt + d4];
    float  A   = g_A[bt];
    float  E   = g_E[bt];

    float4 o;
    o.x = A*(v1h.x - v1l.x) + E*(tot.x - (v0h.x - v0l.x));
    o.y = A*(v1h.y - v1l.y) + E*(tot.y - (v0h.y - v0l.y));
    o.z = A*(v1h.z - v1l.z) + E*(tot.z - (v0h.z - v0l.z));
    o.w = A*(v1h.w - v1l.w) + E*(tot.w - (v0h.w - v0l.w));

    reinterpret_cast<float4*>(out)[idx] = o;
}

extern "C" void kernel_launch(void* const* d_in, const int* in_sizes, int n_in,
                              void* d_out, int out_size) {
    const float* x  = (const float*)d_in[0];   // [B,L,D]
    const float* Wt = (const float*)d_in[1];   // [D,U]
    const float* Wx = (const float*)d_in[2];   // [D,U]
    const float* bh = (const float*)d_in[3];   // [U]
    const float* Wa = (const float*)d_in[4];   // [U,1]
    const float* ba = (const float*)d_in[5];   // [1]
    float* out = (float*)d_out;                // [B,L,D]

    k12<<<BB, 512>>>(x, Wt, Wx, bh, Wa, ba);
    k3_out<<<(BB*LL*DD/4)/256, 256>>>(out);
}

// round 3
// speedup vs baseline: 1.4241x; 1.2991x over previous
#include <cuda_runtime.h>
#include <math.h>

#define BB 8
#define LL 512
#define DD 128
#define UU 32
#define EPSF 1e-7f

// scratch (no allocs allowed)
__device__ __align__(16) float g_wtv[DD];
__device__ __align__(16) float g_wxv[DD];
__device__ float g_c;
__device__ float g_qs[BB*LL];
__device__ float g_ks[BB*LL];
__device__ float g_ek[BB*LL];
__device__ float g_T8[BB*64*DD];   // 8-row partial sums of x
__device__ float g_tot[BB*DD];     // full-row sums of x
__device__ float g_A[BB*LL];       // exp(qc-m)/Z per query
__device__ float g_E[BB*LL];       // exp(-m)/Z per query

// ---------------------------------------------------------------------------
// K0: fold weights. wtv = Wt@Wa, wxv = Wx@Wa, c = bh.Wa + ba
// ---------------------------------------------------------------------------
__global__ void k0_fold(const float* __restrict__ Wt, const float* __restrict__ Wx,
                        const float* __restrict__ bh, const float* __restrict__ Wa,
                        const float* __restrict__ ba) {
    int d = threadIdx.x;
    float at = 0.f, ax = 0.f;
#pragma unroll
    for (int u = 0; u < UU; u++) {
        float wa = Wa[u];
        at += Wt[d*UU + u] * wa;
        ax += Wx[d*UU + u] * wa;
    }
    g_wtv[d] = at;
    g_wxv[d] = ax;
    if (d == 0) {
        float c = ba[0];
#pragma unroll
        for (int u = 0; u < UU; u++) c += bh[u] * Wa[u];
        g_c = c;
    }
}

// ---------------------------------------------------------------------------
// K1: warp-per-token scalars + 8-row partial x sums. grid=512, blk=256
// ---------------------------------------------------------------------------
__global__ __launch_bounds__(256)
void k1(const float* __restrict__ x) {
    int warp = threadIdx.x >> 5;
    int lane = threadIdx.x & 31;
    int token = blockIdx.x * 8 + warp;          // 0..4095, 8 consecutive rows, same batch

    const float4* xr = reinterpret_cast<const float4*>(x + (size_t)token * DD);
    float4 xv = xr[lane];
    float4 wt = reinterpret_cast<const float4*>(g_wtv)[lane];
    float4 wx = reinterpret_cast<const float4*>(g_wxv)[lane];
    float q = xv.x*wt.x + xv.y*wt.y + xv.z*wt.z + xv.w*wt.w;
    float k = xv.x*wx.x + xv.y*wx.y + xv.z*wx.z + xv.w*wx.w;
#pragma unroll
    for (int o = 16; o; o >>= 1) {
        q += __shfl_down_sync(0xFFFFFFFFu, q, o);
        k += __shfl_down_sync(0xFFFFFFFFu, k, o);
    }

    __shared__ __align__(16) float srow[8*DD];
    reinterpret_cast<float4*>(srow)[warp*32 + lane] = xv;
    if (lane == 0) {
        g_qs[token] = q;
        g_ks[token] = k;
        g_ek[token] = expf(k);
    }
    __syncthreads();

    if (threadIdx.x < DD) {
        int d = threadIdx.x;
        float s = 0.f;
#pragma unroll
        for (int w = 0; w < 8; w++) s += srow[w*DD + d];
        g_T8[(size_t)blockIdx.x * DD + d] = s;   // blockIdx = b*64 + j
    }
}

// ---------------------------------------------------------------------------
// K2: per-batch scalars. grid=8, blk=512. No x traffic.
//   scan(ek), window-max, A/Z & E/Z per query, g_T8 -> g_tot
// ---------------------------------------------------------------------------
__global__ __launch_bounds__(512, 1)
void k2(void) {
    int b   = blockIdx.x;
    int tid = threadIdx.x;

    __shared__ float sks[LL];
    __shared__ float scan[2][LL];
    __shared__ float cmax[LL/16];
    __shared__ float tpart[4][DD];

    float ksv = g_ks[b*LL + tid];
    sks[tid] = ksv;
    scan[0][tid] = g_ek[b*LL + tid];
    __syncthreads();

    if (tid < LL/16) {
        float m = sks[tid*16];
#pragma unroll
        for (int i = 1; i < 16; i++) m = fmaxf(m, sks[tid*16 + i]);
        cmax[tid] = m;
    }

    // tot reduction: 4 groups x 128 d, each sums 16 of the 64 T8 rows
    {
        int g = tid >> 7, d = tid & (DD-1);
        float s = 0.f;
#pragma unroll
        for (int j = 0; j < 16; j++)
            s += g_T8[(size_t)(b*64 + g*16 + j)*DD + d];
        tpart[g][d] = s;
    }

    // Hillis-Steele inclusive scan of ek (9 steps)
    int cur = 0;
#pragma unroll
    for (int off = 1; off < LL; off <<= 1) {
        __syncthreads();
        float v = scan[cur][tid];
        if (tid >= off) v += scan[cur][tid - off];
        scan[cur ^ 1][tid] = v;
        cur ^= 1;
    }
    __syncthreads();

    if (tid < DD)
        g_tot[b*DD + tid] = tpart[0][tid] + tpart[1][tid] + tpart[2][tid] + tpart[3][tid];

    // per-query softmax scalars
    {
        int t  = tid;
        int lo = max(0, t - 63);
        int hi = min(LL - 1, t + 64);
        int wc = hi - lo + 1;

        float wm = -INFINITY;
        int c0 = lo >> 4, c1 = hi >> 4;
        int e0 = (c0 + 1) << 4;
        for (int s = lo; s < e0; s++) wm = fmaxf(wm, sks[s]);
        for (int c = c0 + 1; c < c1; c++) wm = fmaxf(wm, cmax[c]);
        for (int s = c1 << 4; s <= hi; s++) wm = fmaxf(wm, sks[s]);

        float qc = g_qs[b*LL + t] + g_c;
        float m  = fmaxf(0.f, qc + wm);     // masked entries score 0, always present (wc<512)
        float A  = expf(qc - m);
        float E  = expf(-m);
        float S1 = scan[cur][hi] - (lo > 0 ? scan[cur][lo-1] : 0.f);
        float Z  = A * S1 + E * (float)(LL - wc) + EPSF;
        float iv = 1.f / Z;
        g_A[b*LL + t] = A * iv;
        g_E[b*LL + t] = E * iv;
    }
}

// ---------------------------------------------------------------------------
// K3: sliding-window output. 8 queries/block, thread = d. grid=512, blk=128
// ---------------------------------------------------------------------------
__global__ __launch_bounds__(128)
void k3(const float* __restrict__ x, float* __restrict__ out) {
    int blk = blockIdx.x;
    int b   = blk >> 6;
    int t0  = (blk & 63) * 8;
    int d   = threadIdx.x;

    const float* xb  = x + (size_t)b * LL * DD;
    const float* ekb = g_ek + b*LL;
    float tot = g_tot[b*DD + d];

    int lo = max(0, t0 - 63);
    int hi = min(LL - 1, t0 + 64);

    // init window sums with 2 accumulator pairs for MLP
    float V0 = 0.f, V1 = 0.f, V0b = 0.f, V1b = 0.f;
    int s = lo;
#pragma unroll 4
    for (; s + 1 <= hi; s += 2) {
        float x0 = __ldg(xb + (size_t)s*DD + d);
        float x1 = __ldg(xb + (size_t)(s+1)*DD + d);
        float e0 = __ldg(ekb + s);
        float e1 = __ldg(ekb + s + 1);
        V0  += x0;  V1  = fmaf(e0, x0, V1);
        V0b += x1;  V1b = fmaf(e1, x1, V1b);
    }
    if (s <= hi) {
        float x0 = __ldg(xb + (size_t)s*DD + d);
        float e0 = __ldg(ekb + s);
        V0 += x0;  V1 = fmaf(e0, x0, V1);
    }
    V0 += V0b;  V1 += V1b;

#pragma unroll
    for (int i = 0; i < 8; i++) {
        int t = t0 + i;
        if (i > 0) {
            int ha = t + 64;   // new hi row (hi(t) = min(511, t+64))
            int ls = t - 64;   // evicted lo row (lo(t) = max(0, t-63))
            if (ha < LL) {
                float xv = __ldg(xb + (size_t)ha*DD + d);
                float e  = __ldg(ekb + ha);
                V0 += xv;  V1 = fmaf(e, xv, V1);
            }
            if (ls >= 0) {
                float xv = __ldg(xb + (size_t)ls*DD + d);
                float e  = __ldg(ekb + ls);
                V0 -= xv;  V1 = fmaf(-e, xv, V1);
            }
        }
        float A = __ldg(g_A + b*LL + t);
        float E = __ldg(g_E + b*LL + t);
        out[((size_t)b*LL + t)*DD + d] = A*V1 + E*(tot - V0);
    }
}

extern "C" void kernel_launch(void* const* d_in, const int* in_sizes, int n_in,
                              void* d_out, int out_size) {
    const float* x  = (const float*)d_in[0];   // [B,L,D]
    const float* Wt = (const float*)d_in[1];   // [D,U]
    const float* Wx = (const float*)d_in[2];   // [D,U]
    const float* bh = (const float*)d_in[3];   // [U]
    const float* Wa = (const float*)d_in[4];   // [U,1]
    const float* ba = (const float*)d_in[5];   // [1]
    float* out = (float*)d_out;                // [B,L,D]

    k0_fold<<<1, DD>>>(Wt, Wx, bh, Wa, ba);
    k1<<<BB*LL/8, 256>>>(x);
    k2<<<BB, 512>>>();
    k3<<<BB*LL/8, 128>>>(x, out);
}

// round 4
// speedup vs baseline: 1.8611x; 1.3069x over previous
#include <cuda_runtime.h>
#include <math.h>

#define BB 8
#define LL 512
#define DD 128
#define UU 32
#define EPSF 1e-7f
#define NC 64            // chunks of 8 rows per batch
#define NSC 8            // superchunks of 64 rows per batch

// scratch (no allocs allowed)
__device__ __align__(16) float g_wtv[DD];
__device__ __align__(16) float g_wxv[DD];
__device__ float g_c;
__device__ float g_qs[BB*LL];
__device__ float g_ks[BB*LL];
__device__ float g_ek[BB*LL];
__device__ float g_T8 [BB*NC*DD];       // chunk-8 sums of x
__device__ float g_T8e[BB*NC*DD];       // chunk-8 sums of ek*x
__device__ float g_SO0[BB*NSC*DD];      // exclusive superchunk offsets (x)
__device__ float g_SO1[BB*NSC*DD];      // exclusive superchunk offsets (ek*x)
__device__ float g_P0[BB*(LL+1)*DD];    // prefix of x over s
__device__ float g_P1[BB*(LL+1)*DD];    // prefix of ek*x over s
__device__ float g_A[BB*LL];            // exp(qc-m)/Z
__device__ float g_E[BB*LL];            // exp(-m)/Z

// ---------------------------------------------------------------------------
// K0: fold weights
// ---------------------------------------------------------------------------
__global__ void k0_fold(const float* __restrict__ Wt, const float* __restrict__ Wx,
                        const float* __restrict__ bh, const float* __restrict__ Wa,
                        const float* __restrict__ ba) {
    int d = threadIdx.x;
    float at = 0.f, ax = 0.f;
#pragma unroll
    for (int u = 0; u < UU; u++) {
        float wa = Wa[u];
        at += Wt[d*UU + u] * wa;
        ax += Wx[d*UU + u] * wa;
    }
    g_wtv[d] = at;
    g_wxv[d] = ax;
    if (d == 0) {
        float c = ba[0];
#pragma unroll
        for (int u = 0; u < UU; u++) c += bh[u] * Wa[u];
        g_c = c;
    }
}

// ---------------------------------------------------------------------------
// K1: warp-per-token scalars + chunk-8 sums. grid=512, blk=256
// ---------------------------------------------------------------------------
__global__ __launch_bounds__(256)
void k1(const float* __restrict__ x) {
    int warp = threadIdx.x >> 5;
    int lane = threadIdx.x & 31;
    int token = blockIdx.x * 8 + warp;          // 8 consecutive rows, same batch

    const float4* xr = reinterpret_cast<const float4*>(x + (size_t)token * DD);
    float4 xv = xr[lane];
    float4 wt = reinterpret_cast<const float4*>(g_wtv)[lane];
    float4 wx = reinterpret_cast<const float4*>(g_wxv)[lane];
    float q = xv.x*wt.x + xv.y*wt.y + xv.z*wt.z + xv.w*wt.w;
    float k = xv.x*wx.x + xv.y*wx.y + xv.z*wx.z + xv.w*wx.w;
#pragma unroll
    for (int o = 16; o; o >>= 1) {
        q += __shfl_down_sync(0xFFFFFFFFu, q, o);
        k += __shfl_down_sync(0xFFFFFFFFu, k, o);
    }

    __shared__ __align__(16) float srow[8*DD];
    __shared__ float sek[8];
    reinterpret_cast<float4*>(srow)[warp*32 + lane] = xv;
    if (lane == 0) {
        float e = expf(k);
        g_qs[token] = q;
        g_ks[token] = k;
        g_ek[token] = e;
        sek[warp] = e;
    }
    __syncthreads();

    if (threadIdx.x < DD) {
        int d = threadIdx.x;
        float s0 = 0.f, s1 = 0.f;
#pragma unroll
        for (int w = 0; w < 8; w++) {
            float v = srow[w*DD + d];
            s0 += v;
            s1 = fmaf(sek[w], v, s1);
        }
        g_T8 [(size_t)blockIdx.x * DD + d] = s0;   // blockIdx = b*64 + chunk
        g_T8e[(size_t)blockIdx.x * DD + d] = s1;
    }
}

// ---------------------------------------------------------------------------
// K2: per-batch: scan(ek) + window max + A/E scalars + superchunk offsets.
//     grid=8, blk=512
// ---------------------------------------------------------------------------
__global__ __launch_bounds__(512, 1)
void k2(void) {
    int b   = blockIdx.x;
    int tid = threadIdx.x;

    __shared__ float sks[LL];
    __shared__ float scan[2][LL];
    __shared__ float cmax[LL/16];
    __shared__ float s8[2][NSC][DD];

    sks[tid]     = g_ks[b*LL + tid];
    scan[0][tid] = g_ek[b*LL + tid];
    __syncthreads();

    if (tid < LL/16) {
        float m = sks[tid*16];
#pragma unroll
        for (int i = 1; i < 16; i++) m = fmaxf(m, sks[tid*16 + i]);
        cmax[tid] = m;
    }

    // superchunk sums from T8: group g handles superchunks g and g+4
    {
        int g = tid >> 7, d = tid & (DD-1);
#pragma unroll
        for (int q = g; q < NSC; q += 4) {
            float a0 = 0.f, a1 = 0.f;
#pragma unroll
            for (int j = 0; j < 8; j++) {
                a0 += g_T8 [(size_t)(b*NC + q*8 + j)*DD + d];
                a1 += g_T8e[(size_t)(b*NC + q*8 + j)*DD + d];
            }
            s8[0][q][d] = a0;
            s8[1][q][d] = a1;
        }
    }

    // Hillis-Steele inclusive scan of ek (9 steps)
    int cur = 0;
#pragma unroll
    for (int off = 1; off < LL; off <<= 1) {
        __syncthreads();
        float v = scan[cur][tid];
        if (tid >= off) v += scan[cur][tid - off];
        scan[cur ^ 1][tid] = v;
        cur ^= 1;
    }
    __syncthreads();

    // exclusive superchunk offsets -> global
    if (tid < DD) {
        int d = tid;
        float r0 = 0.f, r1 = 0.f;
#pragma unroll
        for (int sc = 0; sc < NSC; sc++) {
            g_SO0[(size_t)(b*NSC + sc)*DD + d] = r0;
            g_SO1[(size_t)(b*NSC + sc)*DD + d] = r1;
            r0 += s8[0][sc][d];
            r1 += s8[1][sc][d];
        }
    }

    // per-query softmax scalars
    {
        int t  = tid;
        int lo = max(0, t - 63);
        int hi = min(LL - 1, t + 64);
        int wc = hi - lo + 1;

        float wm = -INFINITY;
        int c0 = lo >> 4, c1 = hi >> 4;
        int e0 = (c0 + 1) << 4;
        for (int s = lo; s < e0; s++) wm = fmaxf(wm, sks[s]);
        for (int c = c0 + 1; c < c1; c++) wm = fmaxf(wm, cmax[c]);
        for (int s = c1 << 4; s <= hi; s++) wm = fmaxf(wm, sks[s]);

        float qc = g_qs[b*LL + t] + g_c;
        float m  = fmaxf(0.f, qc + wm);     // masked entries score 0, always present
        float A  = expf(qc - m);
        float E  = expf(-m);
        float S1 = scan[cur][hi] - (lo > 0 ? scan[cur][lo-1] : 0.f);
        float Z  = A * S1 + E * (float)(LL - wc) + EPSF;
        float iv = 1.f / Z;
        g_A[b*LL + t] = A * iv;
        g_E[b*LL + t] = E * iv;
    }
}

// ---------------------------------------------------------------------------
// K3p: materialize P0/P1. Block = (b, chunk). grid=512, blk=128
// ---------------------------------------------------------------------------
__global__ __launch_bounds__(128)
void k3p(const float* __restrict__ x) {
    int blk = blockIdx.x;
    int b   = blk >> 6;
    int c   = blk & (NC-1);
    int d   = threadIdx.x;

    int sc = c >> 3;
    int j0 = c & ~7;

    float off0 = g_SO0[(size_t)(b*NSC + sc)*DD + d];
    float off1 = g_SO1[(size_t)(b*NSC + sc)*DD + d];
    for (int j = j0; j < c; j++) {           // <=7 independent loads
        off0 += g_T8 [(size_t)(b*NC + j)*DD + d];
        off1 += g_T8e[(size_t)(b*NC + j)*DD + d];
    }

    const float* xb = x + (size_t)b * LL * DD;
    int s0 = c * 8;
    float xr[8], er[8];
#pragma unroll
    for (int i = 0; i < 8; i++) {
        xr[i] = __ldg(xb + (size_t)(s0 + i)*DD + d);
        er[i] = __ldg(g_ek + b*LL + s0 + i);
    }

    size_t base = (size_t)b * (LL+1) * DD;
    if (c == 0) {
        g_P0[base + d] = 0.f;
        g_P1[base + d] = 0.f;
    }
#pragma unroll
    for (int i = 0; i < 8; i++) {
        off0 += xr[i];
        off1 = fmaf(er[i], xr[i], off1);
        g_P0[base + (size_t)(s0 + i + 1)*DD + d] = off0;
        g_P1[base + (size_t)(s0 + i + 1)*DD + d] = off1;
    }
}

// ---------------------------------------------------------------------------
// K4: epilogue, float2 per thread. grid=1024, blk=256
// ---------------------------------------------------------------------------
__global__ __launch_bounds__(256)
void k4(float* __restrict__ out) {
    int idx = blockIdx.x * blockDim.x + threadIdx.x;   // 0 .. BB*LL*DD/2-1
    int bt  = idx >> 6;                                // 64 float2 per row
    int d2  = idx & 63;
    int b   = bt >> 9;
    int t   = bt & (LL-1);

    int lo = max(0, t - 63);
    int hi = min(LL - 1, t + 64);

    size_t base = (size_t)b * (LL+1) * DD;
    const float2* P1 = reinterpret_cast<const float2*>(g_P1);
    const float2* P0 = reinterpret_cast<const float2*>(g_P0);

    size_t rHi = (base + (size_t)(hi+1)*DD) >> 1;
    size_t rLo = (base + (size_t)lo*DD) >> 1;
    size_t rTt = (base + (size_t)LL*DD) >> 1;

    float2 v1h = P1[rHi + d2], v1l = P1[rLo + d2];
    float2 v0h = P0[rHi + d2], v0l = P0[rLo + d2];
    float2 tot = P0[rTt + d2];
    float  A   = g_A[bt];
    float  E   = g_E[bt];

    float2 o;
    o.x = A*(v1h.x - v1l.x) + E*(tot.x - (v0h.x - v0l.x));
    o.y = A*(v1h.y - v1l.y) + E*(tot.y - (v0h.y - v0l.y));

    reinterpret_cast<float2*>(out)[idx] = o;
}

extern "C" void kernel_launch(void* const* d_in, const int* in_sizes, int n_in,
                              void* d_out, int out_size) {
    const float* x  = (const float*)d_in[0];   // [B,L,D]
    const float* Wt = (const float*)d_in[1];   // [D,U]
    const float* Wx = (const float*)d_in[2];   // [D,U]
    const float* bh = (const float*)d_in[3];   // [U]
    const float* Wa = (const float*)d_in[4];   // [U,1]
    const float* ba = (const float*)d_in[5];   // [1]
    float* out = (float*)d_out;                // [B,L,D]

    k0_fold<<<1, DD>>>(Wt, Wx, bh, Wa, ba);
    k1<<<BB*LL/8, 256>>>(x);
    k2<<<BB, 512>>>();
    k3p<<<BB*NC, DD>>>(x);
    k4<<<(BB*LL*DD/2)/256, 256>>>(out);
}